// round 5
// baseline (speedup 1.0000x reference)
#include <cuda_runtime.h>
#include <cstdint>

#define N_NODES 50000
#define N_EDGES 800000
#define F_IN   128
#define F_HID  64
#define F_OUT  40
#define SCAN_B 1024
#define SCAN_NB ((N_NODES + SCAN_B - 1) / SCAN_B)   // 49

// ---------------- scratch (device globals: no allocation allowed) ----------
__device__ float g_h[N_NODES * 64];      // GEMM output h' (dinv-prescaled)
__device__ float g_z[N_NODES * 64];      // activation buffer
__device__ int   g_dege[N_NODES];        // edge-only degree (no self loop)
__device__ int   g_cursor[N_NODES];
__device__ int   g_rowstart[N_NODES];
__device__ int   g_csrc[N_EDGES];
__device__ int   g_bsum[SCAN_NB];
__device__ float g_dinv[N_NODES];

// ---------------- degree count ---------------------------------------------
__global__ void deg_count_k(const int* __restrict__ dst, int* __restrict__ dege) {
    int e = blockIdx.x * blockDim.x + threadIdx.x;
    if (e < N_EDGES) atomicAdd(&dege[dst[e]], 1);
}

// ---------------- fused scan + dinv + cursor init --------------------------
// two-level warp-shuffle scan (2 barriers); also computes dinv = rsqrt(deg+1)
// and zeroes the fill cursor.
__global__ __launch_bounds__(SCAN_B)
void scan1_k(const int* __restrict__ dege, int* __restrict__ rowstart,
             int* __restrict__ bsum, float* __restrict__ dinv,
             int* __restrict__ cursor)
{
    __shared__ int warpsum[32];
    const int t = threadIdx.x;
    const int lane = t & 31;
    const int wid = t >> 5;
    const int g = blockIdx.x * SCAN_B + t;

    int v = (g < N_NODES) ? dege[g] : 0;

    // inclusive warp scan
    int x = v;
    #pragma unroll
    for (int off = 1; off < 32; off <<= 1) {
        int y = __shfl_up_sync(0xFFFFFFFFu, x, off);
        if (lane >= off) x += y;
    }
    if (lane == 31) warpsum[wid] = x;
    __syncthreads();
    if (t < 32) {
        int w = warpsum[t];
        #pragma unroll
        for (int off = 1; off < 32; off <<= 1) {
            int y = __shfl_up_sync(0xFFFFFFFFu, w, off);
            if (t >= off) w += y;
        }
        warpsum[t] = w;
    }
    __syncthreads();

    int base = (wid > 0) ? warpsum[wid - 1] : 0;
    int incl = base + x;
    if (g < N_NODES) {
        rowstart[g] = incl - v;              // exclusive
        dinv[g] = rsqrtf((float)(v + 1));
        cursor[g] = 0;
    }
    if (t == SCAN_B - 1) bsum[blockIdx.x] = incl;
}

__global__ void scan2_k(int* __restrict__ bsum) {
    __shared__ int s[64];
    int t = threadIdx.x;
    int v = (t < SCAN_NB) ? bsum[t] : 0;
    s[t] = v;
    __syncthreads();
    #pragma unroll
    for (int off = 1; off < 64; off <<= 1) {
        int x = (t >= off) ? s[t - off] : 0;
        __syncthreads();
        s[t] += x;
        __syncthreads();
    }
    if (t < SCAN_NB) bsum[t] = s[t] - v;     // exclusive block offsets
}

__global__ __launch_bounds__(SCAN_B)
void scan3_k(int* __restrict__ rowstart, const int* __restrict__ bsum) {
    int t = threadIdx.x;
    int g = blockIdx.x * SCAN_B + t;
    if (g < N_NODES) rowstart[g] += bsum[blockIdx.x];
}

__global__ void fill_k(const int* __restrict__ src, const int* __restrict__ dst,
                       const int* __restrict__ rowstart, int* __restrict__ cursor,
                       int* __restrict__ csrc) {
    int e = blockIdx.x * blockDim.x + threadIdx.x;
    if (e < N_EDGES) {
        int d = dst[e];
        int pos = rowstart[d] + atomicAdd(&cursor[d], 1);
        csrc[pos] = src[e];
    }
}

// ---------------- GEMM: C = (A[N,M] @ W[M,K]) * dinv[row] ------------------
// BM=128, BN=64, BK=16, 256 threads, 8x4 micro-tile. A-tile stored transposed.
__global__ __launch_bounds__(256)
void gemm_scaled_k(const float* __restrict__ A, const float* __restrict__ W,
                   const float* __restrict__ dinv, float* __restrict__ C,
                   int M, int K)
{
    __shared__ float As[16][132];   // [k][row], padded against store conflicts
    __shared__ float Ws[16][64];    // [k][col]

    const int tid = threadIdx.x;
    const int tx  = tid & 15;            // col group: cols tx*4 .. +3
    const int ty  = tid >> 4;            // row group: rows ty*8 .. +7
    const int n0  = blockIdx.x * 128;

    const int aRow = tid >> 2;           // 0..63
    const int aCol = (tid & 3) << 2;     // 0,4,8,12
    const int wRow = tid >> 4;           // 0..15
    const int wCol = (tid & 15) << 2;    // 0..60

    float acc[8][4] = {};

    for (int k0 = 0; k0 < M; k0 += 16) {
        #pragma unroll
        for (int hh = 0; hh < 2; hh++) {
            int row = aRow + hh * 64;
            float4 av = make_float4(0.f, 0.f, 0.f, 0.f);
            if (n0 + row < N_NODES)
                av = *(const float4*)(A + (size_t)(n0 + row) * M + k0 + aCol);
            As[aCol + 0][row] = av.x;
            As[aCol + 1][row] = av.y;
            As[aCol + 2][row] = av.z;
            As[aCol + 3][row] = av.w;
        }
        float4 wv = make_float4(0.f, 0.f, 0.f, 0.f);
        if (wCol < K)
            wv = *(const float4*)(W + (size_t)(k0 + wRow) * K + wCol);
        *(float4*)&Ws[wRow][wCol] = wv;

        __syncthreads();

        #pragma unroll
        for (int k = 0; k < 16; k++) {
            float4 a0 = *(const float4*)&As[k][ty * 8];
            float4 a1 = *(const float4*)&As[k][ty * 8 + 4];
            float4 b  = *(const float4*)&Ws[k][tx * 4];
            float ar[8] = {a0.x, a0.y, a0.z, a0.w, a1.x, a1.y, a1.z, a1.w};
            #pragma unroll
            for (int i = 0; i < 8; i++) {
                acc[i][0] += ar[i] * b.x;
                acc[i][1] += ar[i] * b.y;
                acc[i][2] += ar[i] * b.z;
                acc[i][3] += ar[i] * b.w;
            }
        }
        __syncthreads();
    }

    const int colBase = tx << 2;
    if (colBase < K) {
        #pragma unroll
        for (int i = 0; i < 8; i++) {
            int row = n0 + ty * 8 + i;
            if (row < N_NODES) {
                float s = dinv[row];
                float4 v;
                v.x = acc[i][0] * s; v.y = acc[i][1] * s;
                v.z = acc[i][2] * s; v.w = acc[i][3] * s;
                *(float4*)(C + (size_t)row * K + colBase) = v;
            }
        }
    }
}

// ---------------- fused CSR aggregation + epilogue -------------------------
// z[d] = act( dinv[d] * ( h'[d] + sum_{s in N(d)} h'[s] ) + bias )
// 16 consecutive threads per node, each owns one float4 column slice.
// 4-way unrolled gather loop: 4 independent row gathers in flight per thread.
template<int F, bool RELU>
__global__ __launch_bounds__(256)
void agg_fused_k(const float* __restrict__ h, const int* __restrict__ rowstart,
                 const int* __restrict__ dege, const int* __restrict__ csrc,
                 const float* __restrict__ dinv, const float* __restrict__ bias,
                 float* __restrict__ z)
{
    unsigned t = blockIdx.x * blockDim.x + threadIdx.x;
    unsigned node = t >> 4;
    unsigned j = (t & 15) << 2;
    if (node >= N_NODES) return;
    const bool active = (j < F);

    float4 acc0 = make_float4(0.f, 0.f, 0.f, 0.f);
    float4 acc1 = make_float4(0.f, 0.f, 0.f, 0.f);
    if (active)
        acc0 = *(const float4*)(h + (size_t)node * F + j);   // self loop

    int i   = rowstart[node];
    int end = i + dege[node];

    for (; i + 4 <= end; i += 4) {
        int p0 = __ldg(&csrc[i + 0]);
        int p1 = __ldg(&csrc[i + 1]);
        int p2 = __ldg(&csrc[i + 2]);
        int p3 = __ldg(&csrc[i + 3]);
        if (active) {
            float4 v0 = __ldg((const float4*)(h + (size_t)p0 * F + j));
            float4 v1 = __ldg((const float4*)(h + (size_t)p1 * F + j));
            float4 v2 = __ldg((const float4*)(h + (size_t)p2 * F + j));
            float4 v3 = __ldg((const float4*)(h + (size_t)p3 * F + j));
            acc0.x += v0.x; acc0.y += v0.y; acc0.z += v0.z; acc0.w += v0.w;
            acc1.x += v1.x; acc1.y += v1.y; acc1.z += v1.z; acc1.w += v1.w;
            acc0.x += v2.x; acc0.y += v2.y; acc0.z += v2.z; acc0.w += v2.w;
            acc1.x += v3.x; acc1.y += v3.y; acc1.z += v3.z; acc1.w += v3.w;
        }
    }
    for (; i < end; i++) {
        int p = __ldg(&csrc[i]);
        if (active) {
            float4 v = __ldg((const float4*)(h + (size_t)p * F + j));
            acc0.x += v.x; acc0.y += v.y; acc0.z += v.z; acc0.w += v.w;
        }
    }

    if (active) {
        float sc = dinv[node];
        float4 b = *(const float4*)(bias + j);
        acc0.x += acc1.x; acc0.y += acc1.y; acc0.z += acc1.z; acc0.w += acc1.w;
        acc0.x = fmaf(acc0.x, sc, b.x);
        acc0.y = fmaf(acc0.y, sc, b.y);
        acc0.z = fmaf(acc0.z, sc, b.z);
        acc0.w = fmaf(acc0.w, sc, b.w);
        if (RELU) {
            acc0.x = fmaxf(acc0.x, 0.f); acc0.y = fmaxf(acc0.y, 0.f);
            acc0.z = fmaxf(acc0.z, 0.f); acc0.w = fmaxf(acc0.w, 0.f);
        }
        *(float4*)(z + (size_t)node * F + j) = acc0;
    }
}

// ---------------- launch ---------------------------------------------------
extern "C" void kernel_launch(void* const* d_in, const int* in_sizes, int n_in,
                              void* d_out, int out_size)
{
    const float* x  = (const float*)d_in[0];
    const int*   ei = (const int*)  d_in[1];
    const float* W1 = (const float*)d_in[2];
    const float* b1 = (const float*)d_in[3];
    const float* W2 = (const float*)d_in[4];
    const float* b2 = (const float*)d_in[5];
    const float* W3 = (const float*)d_in[6];
    const float* b3 = (const float*)d_in[7];
    float* out = (float*)d_out;

    const int* src = ei;              // edge_index[0]
    const int* dst = ei + N_EDGES;    // edge_index[1]

    float *h, *z, *dinv;
    int *dege, *cursor, *rowstart, *csrc, *bsum;
    cudaGetSymbolAddress((void**)&h,        g_h);
    cudaGetSymbolAddress((void**)&z,        g_z);
    cudaGetSymbolAddress((void**)&dinv,     g_dinv);
    cudaGetSymbolAddress((void**)&dege,     g_dege);
    cudaGetSymbolAddress((void**)&cursor,   g_cursor);
    cudaGetSymbolAddress((void**)&rowstart, g_rowstart);
    cudaGetSymbolAddress((void**)&csrc,     g_csrc);
    cudaGetSymbolAddress((void**)&bsum,     g_bsum);

    const int TPB = 256;
    const int edgeBlocks = (N_EDGES + TPB - 1) / TPB;
    const int gemmBlocks = (N_NODES + 127) / 128;
    const int aggBlocks  = ((unsigned)N_NODES * 16 + TPB - 1) / TPB;

    // ---- CSR build + normalization ----
    cudaMemsetAsync(dege, 0, N_NODES * sizeof(int));
    deg_count_k<<<edgeBlocks, TPB>>>(dst, dege);
    scan1_k    <<<SCAN_NB, SCAN_B>>>(dege, rowstart, bsum, dinv, cursor);
    scan2_k    <<<1, 64>>>(bsum);
    scan3_k    <<<SCAN_NB, SCAN_B>>>(rowstart, bsum);
    fill_k     <<<edgeBlocks, TPB>>>(src, dst, rowstart, cursor, csrc);

    // ---- layer 1: x[50000,128] @ W1[128,64] ----
    gemm_scaled_k<<<gemmBlocks, TPB>>>(x, W1, dinv, h, F_IN, F_HID);
    agg_fused_k<F_HID, true><<<aggBlocks, TPB>>>(h, rowstart, dege, csrc, dinv, b1, z);

    // ---- layer 2: z1 @ W2[64,64] ----
    gemm_scaled_k<<<gemmBlocks, TPB>>>(z, W2, dinv, h, F_HID, F_HID);
    agg_fused_k<F_HID, true><<<aggBlocks, TPB>>>(h, rowstart, dege, csrc, dinv, b2, z);

    // ---- layer 3: z2 @ W3[64,40] -> d_out ----
    gemm_scaled_k<<<gemmBlocks, TPB>>>(z, W3, dinv, h, F_HID, F_OUT);
    agg_fused_k<F_OUT, false><<<aggBlocks, TPB>>>(h, rowstart, dege, csrc, dinv, b3, out);
}

// round 6
// speedup vs baseline: 1.0085x; 1.0085x over previous
#include <cuda_runtime.h>
#include <cstdint>

#define N_NODES 50000
#define N_EDGES 800000
#define F_IN   128
#define F_HID  64
#define F_OUT  40
#define SCAN_B 1024
#define SCAN_NB ((N_NODES + SCAN_B - 1) / SCAN_B)   // 49

// ---------------- scratch (device globals: no allocation allowed) ----------
__device__ float g_h[N_NODES * 64];      // GEMM output h' (dinv-prescaled)
__device__ float g_z[N_NODES * 64];      // activation buffer
__device__ int   g_dege[N_NODES];        // edge-only degree (no self loop)
__device__ int   g_cursor[N_NODES];
__device__ int   g_rowstart[N_NODES];
__device__ int   g_csrc[N_EDGES];
__device__ int   g_bsum[SCAN_NB];
__device__ float g_dinv[N_NODES];

// ---------------- degree count ---------------------------------------------
__global__ void deg_count_k(const int* __restrict__ dst, int* __restrict__ dege) {
    int e = blockIdx.x * blockDim.x + threadIdx.x;
    if (e < N_EDGES) atomicAdd(&dege[dst[e]], 1);
}

// ---------------- fused scan + dinv + cursor init --------------------------
// two-level warp-shuffle scan (2 barriers); also computes dinv = rsqrt(deg+1)
// and zeroes the fill cursor.
__global__ __launch_bounds__(SCAN_B)
void scan1_k(const int* __restrict__ dege, int* __restrict__ rowstart,
             int* __restrict__ bsum, float* __restrict__ dinv,
             int* __restrict__ cursor)
{
    __shared__ int warpsum[32];
    const int t = threadIdx.x;
    const int lane = t & 31;
    const int wid = t >> 5;
    const int g = blockIdx.x * SCAN_B + t;

    int v = (g < N_NODES) ? dege[g] : 0;

    // inclusive warp scan
    int x = v;
    #pragma unroll
    for (int off = 1; off < 32; off <<= 1) {
        int y = __shfl_up_sync(0xFFFFFFFFu, x, off);
        if (lane >= off) x += y;
    }
    if (lane == 31) warpsum[wid] = x;
    __syncthreads();
    if (t < 32) {
        int w = warpsum[t];
        #pragma unroll
        for (int off = 1; off < 32; off <<= 1) {
            int y = __shfl_up_sync(0xFFFFFFFFu, w, off);
            if (t >= off) w += y;
        }
        warpsum[t] = w;
    }
    __syncthreads();

    int base = (wid > 0) ? warpsum[wid - 1] : 0;
    int incl = base + x;
    if (g < N_NODES) {
        rowstart[g] = incl - v;              // exclusive
        dinv[g] = rsqrtf((float)(v + 1));
        cursor[g] = 0;
    }
    if (t == SCAN_B - 1) bsum[blockIdx.x] = incl;
}

__global__ void scan2_k(int* __restrict__ bsum) {
    __shared__ int s[64];
    int t = threadIdx.x;
    int v = (t < SCAN_NB) ? bsum[t] : 0;
    s[t] = v;
    __syncthreads();
    #pragma unroll
    for (int off = 1; off < 64; off <<= 1) {
        int x = (t >= off) ? s[t - off] : 0;
        __syncthreads();
        s[t] += x;
        __syncthreads();
    }
    if (t < SCAN_NB) bsum[t] = s[t] - v;     // exclusive block offsets
}

__global__ __launch_bounds__(SCAN_B)
void scan3_k(int* __restrict__ rowstart, const int* __restrict__ bsum) {
    int t = threadIdx.x;
    int g = blockIdx.x * SCAN_B + t;
    if (g < N_NODES) rowstart[g] += bsum[blockIdx.x];
}

__global__ void fill_k(const int* __restrict__ src, const int* __restrict__ dst,
                       const int* __restrict__ rowstart, int* __restrict__ cursor,
                       int* __restrict__ csrc) {
    int e = blockIdx.x * blockDim.x + threadIdx.x;
    if (e < N_EDGES) {
        int d = dst[e];
        int pos = rowstart[d] + atomicAdd(&cursor[d], 1);
        csrc[pos] = src[e];
    }
}

// ---------------- GEMM: C = (A[N,M] @ W[M,K]) * dinv[row] ------------------
// BM=128, BN=64, BK=16, 256 threads, 8x4 micro-tile. A-tile stored transposed.
__global__ __launch_bounds__(256)
void gemm_scaled_k(const float* __restrict__ A, const float* __restrict__ W,
                   const float* __restrict__ dinv, float* __restrict__ C,
                   int M, int K)
{
    __shared__ float As[16][132];   // [k][row], padded against store conflicts
    __shared__ float Ws[16][64];    // [k][col]

    const int tid = threadIdx.x;
    const int tx  = tid & 15;            // col group: cols tx*4 .. +3
    const int ty  = tid >> 4;            // row group: rows ty*8 .. +7
    const int n0  = blockIdx.x * 128;

    const int aRow = tid >> 2;           // 0..63
    const int aCol = (tid & 3) << 2;     // 0,4,8,12
    const int wRow = tid >> 4;           // 0..15
    const int wCol = (tid & 15) << 2;    // 0..60

    float acc[8][4] = {};

    for (int k0 = 0; k0 < M; k0 += 16) {
        #pragma unroll
        for (int hh = 0; hh < 2; hh++) {
            int row = aRow + hh * 64;
            float4 av = make_float4(0.f, 0.f, 0.f, 0.f);
            if (n0 + row < N_NODES)
                av = *(const float4*)(A + (size_t)(n0 + row) * M + k0 + aCol);
            As[aCol + 0][row] = av.x;
            As[aCol + 1][row] = av.y;
            As[aCol + 2][row] = av.z;
            As[aCol + 3][row] = av.w;
        }
        float4 wv = make_float4(0.f, 0.f, 0.f, 0.f);
        if (wCol < K)
            wv = *(const float4*)(W + (size_t)(k0 + wRow) * K + wCol);
        *(float4*)&Ws[wRow][wCol] = wv;

        __syncthreads();

        #pragma unroll
        for (int k = 0; k < 16; k++) {
            float4 a0 = *(const float4*)&As[k][ty * 8];
            float4 a1 = *(const float4*)&As[k][ty * 8 + 4];
            float4 b  = *(const float4*)&Ws[k][tx * 4];
            float ar[8] = {a0.x, a0.y, a0.z, a0.w, a1.x, a1.y, a1.z, a1.w};
            #pragma unroll
            for (int i = 0; i < 8; i++) {
                acc[i][0] += ar[i] * b.x;
                acc[i][1] += ar[i] * b.y;
                acc[i][2] += ar[i] * b.z;
                acc[i][3] += ar[i] * b.w;
            }
        }
        __syncthreads();
    }

    const int colBase = tx << 2;
    if (colBase < K) {
        #pragma unroll
        for (int i = 0; i < 8; i++) {
            int row = n0 + ty * 8 + i;
            if (row < N_NODES) {
                float s = dinv[row];
                float4 v;
                v.x = acc[i][0] * s; v.y = acc[i][1] * s;
                v.z = acc[i][2] * s; v.w = acc[i][3] * s;
                *(float4*)(C + (size_t)row * K + colBase) = v;
            }
        }
    }
}

// ---------------- fused CSR aggregation + epilogue -------------------------
// z[d] = act( dinv[d] * ( h'[d] + sum_{s in N(d)} h'[s] ) + bias )
// 16 consecutive threads per node, each owns one float4 column slice.
// 4-way unrolled gather loop: 4 independent row gathers in flight per thread.
template<int F, bool RELU>
__global__ __launch_bounds__(256)
void agg_fused_k(const float* __restrict__ h, const int* __restrict__ rowstart,
                 const int* __restrict__ dege, const int* __restrict__ csrc,
                 const float* __restrict__ dinv, const float* __restrict__ bias,
                 float* __restrict__ z)
{
    unsigned t = blockIdx.x * blockDim.x + threadIdx.x;
    unsigned node = t >> 4;
    unsigned j = (t & 15) << 2;
    if (node >= N_NODES) return;
    const bool active = (j < F);

    float4 acc0 = make_float4(0.f, 0.f, 0.f, 0.f);
    float4 acc1 = make_float4(0.f, 0.f, 0.f, 0.f);
    if (active)
        acc0 = *(const float4*)(h + (size_t)node * F + j);   // self loop

    int i   = rowstart[node];
    int end = i + dege[node];

    for (; i + 4 <= end; i += 4) {
        int p0 = __ldg(&csrc[i + 0]);
        int p1 = __ldg(&csrc[i + 1]);
        int p2 = __ldg(&csrc[i + 2]);
        int p3 = __ldg(&csrc[i + 3]);
        if (active) {
            float4 v0 = __ldg((const float4*)(h + (size_t)p0 * F + j));
            float4 v1 = __ldg((const float4*)(h + (size_t)p1 * F + j));
            float4 v2 = __ldg((const float4*)(h + (size_t)p2 * F + j));
            float4 v3 = __ldg((const float4*)(h + (size_t)p3 * F + j));
            acc0.x += v0.x; acc0.y += v0.y; acc0.z += v0.z; acc0.w += v0.w;
            acc1.x += v1.x; acc1.y += v1.y; acc1.z += v1.z; acc1.w += v1.w;
            acc0.x += v2.x; acc0.y += v2.y; acc0.z += v2.z; acc0.w += v2.w;
            acc1.x += v3.x; acc1.y += v3.y; acc1.z += v3.z; acc1.w += v3.w;
        }
    }
    for (; i < end; i++) {
        int p = __ldg(&csrc[i]);
        if (active) {
            float4 v = __ldg((const float4*)(h + (size_t)p * F + j));
            acc0.x += v.x; acc0.y += v.y; acc0.z += v.z; acc0.w += v.w;
        }
    }

    if (active) {
        float sc = dinv[node];
        float4 b = *(const float4*)(bias + j);
        acc0.x += acc1.x; acc0.y += acc1.y; acc0.z += acc1.z; acc0.w += acc1.w;
        acc0.x = fmaf(acc0.x, sc, b.x);
        acc0.y = fmaf(acc0.y, sc, b.y);
        acc0.z = fmaf(acc0.z, sc, b.z);
        acc0.w = fmaf(acc0.w, sc, b.w);
        if (RELU) {
            acc0.x = fmaxf(acc0.x, 0.f); acc0.y = fmaxf(acc0.y, 0.f);
            acc0.z = fmaxf(acc0.z, 0.f); acc0.w = fmaxf(acc0.w, 0.f);
        }
        *(float4*)(z + (size_t)node * F + j) = acc0;
    }
}

// ---------------- launch ---------------------------------------------------
extern "C" void kernel_launch(void* const* d_in, const int* in_sizes, int n_in,
                              void* d_out, int out_size)
{
    const float* x  = (const float*)d_in[0];
    const int*   ei = (const int*)  d_in[1];
    const float* W1 = (const float*)d_in[2];
    const float* b1 = (const float*)d_in[3];
    const float* W2 = (const float*)d_in[4];
    const float* b2 = (const float*)d_in[5];
    const float* W3 = (const float*)d_in[6];
    const float* b3 = (const float*)d_in[7];
    float* out = (float*)d_out;

    const int* src = ei;              // edge_index[0]
    const int* dst = ei + N_EDGES;    // edge_index[1]

    float *h, *z, *dinv;
    int *dege, *cursor, *rowstart, *csrc, *bsum;
    cudaGetSymbolAddress((void**)&h,        g_h);
    cudaGetSymbolAddress((void**)&z,        g_z);
    cudaGetSymbolAddress((void**)&dinv,     g_dinv);
    cudaGetSymbolAddress((void**)&dege,     g_dege);
    cudaGetSymbolAddress((void**)&cursor,   g_cursor);
    cudaGetSymbolAddress((void**)&rowstart, g_rowstart);
    cudaGetSymbolAddress((void**)&csrc,     g_csrc);
    cudaGetSymbolAddress((void**)&bsum,     g_bsum);

    const int TPB = 256;
    const int edgeBlocks = (N_EDGES + TPB - 1) / TPB;
    const int gemmBlocks = (N_NODES + 127) / 128;
    const int aggBlocks  = ((unsigned)N_NODES * 16 + TPB - 1) / TPB;

    // ---- CSR build + normalization ----
    cudaMemsetAsync(dege, 0, N_NODES * sizeof(int));
    deg_count_k<<<edgeBlocks, TPB>>>(dst, dege);
    scan1_k    <<<SCAN_NB, SCAN_B>>>(dege, rowstart, bsum, dinv, cursor);
    scan2_k    <<<1, 64>>>(bsum);
    scan3_k    <<<SCAN_NB, SCAN_B>>>(rowstart, bsum);
    fill_k     <<<edgeBlocks, TPB>>>(src, dst, rowstart, cursor, csrc);

    // ---- layer 1: x[50000,128] @ W1[128,64] ----
    gemm_scaled_k<<<gemmBlocks, TPB>>>(x, W1, dinv, h, F_IN, F_HID);
    agg_fused_k<F_HID, true><<<aggBlocks, TPB>>>(h, rowstart, dege, csrc, dinv, b1, z);

    // ---- layer 2: z1 @ W2[64,64] ----
    gemm_scaled_k<<<gemmBlocks, TPB>>>(z, W2, dinv, h, F_HID, F_HID);
    agg_fused_k<F_HID, true><<<aggBlocks, TPB>>>(h, rowstart, dege, csrc, dinv, b2, z);

    // ---- layer 3: z2 @ W3[64,40] -> d_out ----
    gemm_scaled_k<<<gemmBlocks, TPB>>>(z, W3, dinv, h, F_HID, F_OUT);
    agg_fused_k<F_OUT, false><<<aggBlocks, TPB>>>(h, rowstart, dege, csrc, dinv, b3, out);
}

// round 7
// speedup vs baseline: 1.0255x; 1.0168x over previous
#include <cuda_runtime.h>
#include <cstdint>

#define N_NODES 50000
#define N_EDGES 800000
#define F_IN   128
#define F_HID  64
#define F_OUT  40
#define SCAN_B 1024
#define SCAN_NB ((N_NODES + SCAN_B - 1) / SCAN_B)   // 49

// ---------------- scratch (device globals: no allocation allowed) ----------
__device__ float g_h[N_NODES * 64];      // GEMM output h' (dinv-prescaled)
__device__ float g_z[N_NODES * 64];      // activation buffer
__device__ int   g_dege[N_NODES];        // edge-only degree (no self loop)
__device__ int   g_cursor[N_NODES];
__device__ int   g_rowstart[N_NODES];
__device__ int   g_csrc[N_EDGES];
__device__ int   g_bsum[SCAN_NB];
__device__ float g_dinv[N_NODES];

// ---------------- degree count ---------------------------------------------
__global__ void deg_count_k(const int* __restrict__ dst, int* __restrict__ dege) {
    int e = blockIdx.x * blockDim.x + threadIdx.x;
    if (e < N_EDGES) atomicAdd(&dege[dst[e]], 1);
}

// ---------------- fused scan + dinv + cursor init --------------------------
// two-level warp-shuffle scan (2 barriers); also computes dinv = rsqrt(deg+1)
// and zeroes the fill cursor.
__global__ __launch_bounds__(SCAN_B)
void scan1_k(const int* __restrict__ dege, int* __restrict__ rowstart,
             int* __restrict__ bsum, float* __restrict__ dinv,
             int* __restrict__ cursor)
{
    __shared__ int warpsum[32];
    const int t = threadIdx.x;
    const int lane = t & 31;
    const int wid = t >> 5;
    const int g = blockIdx.x * SCAN_B + t;

    int v = (g < N_NODES) ? dege[g] : 0;

    // inclusive warp scan
    int x = v;
    #pragma unroll
    for (int off = 1; off < 32; off <<= 1) {
        int y = __shfl_up_sync(0xFFFFFFFFu, x, off);
        if (lane >= off) x += y;
    }
    if (lane == 31) warpsum[wid] = x;
    __syncthreads();
    if (t < 32) {
        int w = warpsum[t];
        #pragma unroll
        for (int off = 1; off < 32; off <<= 1) {
            int y = __shfl_up_sync(0xFFFFFFFFu, w, off);
            if (t >= off) w += y;
        }
        warpsum[t] = w;
    }
    __syncthreads();

    int base = (wid > 0) ? warpsum[wid - 1] : 0;
    int incl = base + x;
    if (g < N_NODES) {
        rowstart[g] = incl - v;              // exclusive
        dinv[g] = rsqrtf((float)(v + 1));
        cursor[g] = 0;
    }
    if (t == SCAN_B - 1) bsum[blockIdx.x] = incl;
}

__global__ void scan2_k(int* __restrict__ bsum) {
    __shared__ int s[64];
    int t = threadIdx.x;
    int v = (t < SCAN_NB) ? bsum[t] : 0;
    s[t] = v;
    __syncthreads();
    #pragma unroll
    for (int off = 1; off < 64; off <<= 1) {
        int x = (t >= off) ? s[t - off] : 0;
        __syncthreads();
        s[t] += x;
        __syncthreads();
    }
    if (t < SCAN_NB) bsum[t] = s[t] - v;     // exclusive block offsets
}

__global__ __launch_bounds__(SCAN_B)
void scan3_k(int* __restrict__ rowstart, const int* __restrict__ bsum) {
    int t = threadIdx.x;
    int g = blockIdx.x * SCAN_B + t;
    if (g < N_NODES) rowstart[g] += bsum[blockIdx.x];
}

__global__ void fill_k(const int* __restrict__ src, const int* __restrict__ dst,
                       const int* __restrict__ rowstart, int* __restrict__ cursor,
                       int* __restrict__ csrc) {
    int e = blockIdx.x * blockDim.x + threadIdx.x;
    if (e < N_EDGES) {
        int d = dst[e];
        int pos = rowstart[d] + atomicAdd(&cursor[d], 1);
        csrc[pos] = src[e];
    }
}

// ---------------- GEMM: C = (A[N,M] @ W[M,K]) * dinv[row] ------------------
// BM=128, BN=64, BK=16, 256 threads, 8x4 micro-tile. A-tile stored transposed.
__global__ __launch_bounds__(256)
void gemm_scaled_k(const float* __restrict__ A, const float* __restrict__ W,
                   const float* __restrict__ dinv, float* __restrict__ C,
                   int M, int K)
{
    __shared__ float As[16][132];   // [k][row], padded against store conflicts
    __shared__ float Ws[16][64];    // [k][col]

    const int tid = threadIdx.x;
    const int tx  = tid & 15;            // col group: cols tx*4 .. +3
    const int ty  = tid >> 4;            // row group: rows ty*8 .. +7
    const int n0  = blockIdx.x * 128;

    const int aRow = tid >> 2;           // 0..63
    const int aCol = (tid & 3) << 2;     // 0,4,8,12
    const int wRow = tid >> 4;           // 0..15
    const int wCol = (tid & 15) << 2;    // 0..60

    float acc[8][4] = {};

    for (int k0 = 0; k0 < M; k0 += 16) {
        #pragma unroll
        for (int hh = 0; hh < 2; hh++) {
            int row = aRow + hh * 64;
            float4 av = make_float4(0.f, 0.f, 0.f, 0.f);
            if (n0 + row < N_NODES)
                av = *(const float4*)(A + (size_t)(n0 + row) * M + k0 + aCol);
            As[aCol + 0][row] = av.x;
            As[aCol + 1][row] = av.y;
            As[aCol + 2][row] = av.z;
            As[aCol + 3][row] = av.w;
        }
        float4 wv = make_float4(0.f, 0.f, 0.f, 0.f);
        if (wCol < K)
            wv = *(const float4*)(W + (size_t)(k0 + wRow) * K + wCol);
        *(float4*)&Ws[wRow][wCol] = wv;

        __syncthreads();

        #pragma unroll
        for (int k = 0; k < 16; k++) {
            float4 a0 = *(const float4*)&As[k][ty * 8];
            float4 a1 = *(const float4*)&As[k][ty * 8 + 4];
            float4 b  = *(const float4*)&Ws[k][tx * 4];
            float ar[8] = {a0.x, a0.y, a0.z, a0.w, a1.x, a1.y, a1.z, a1.w};
            #pragma unroll
            for (int i = 0; i < 8; i++) {
                acc[i][0] += ar[i] * b.x;
                acc[i][1] += ar[i] * b.y;
                acc[i][2] += ar[i] * b.z;
                acc[i][3] += ar[i] * b.w;
            }
        }
        __syncthreads();
    }

    const int colBase = tx << 2;
    if (colBase < K) {
        #pragma unroll
        for (int i = 0; i < 8; i++) {
            int row = n0 + ty * 8 + i;
            if (row < N_NODES) {
                float s = dinv[row];
                float4 v;
                v.x = acc[i][0] * s; v.y = acc[i][1] * s;
                v.z = acc[i][2] * s; v.w = acc[i][3] * s;
                *(float4*)(C + (size_t)row * K + colBase) = v;
            }
        }
    }
}

// ---------------- fused CSR aggregation + epilogue -------------------------
// z[d] = act( dinv[d] * ( h'[d] + sum_{s in N(d)} h'[s] ) + bias )
// 16 consecutive threads per node, each owns one float4 column slice.
// 4-way unrolled gather loop: 4 independent row gathers in flight per thread.
template<int F, bool RELU>
__global__ __launch_bounds__(256)
void agg_fused_k(const float* __restrict__ h, const int* __restrict__ rowstart,
                 const int* __restrict__ dege, const int* __restrict__ csrc,
                 const float* __restrict__ dinv, const float* __restrict__ bias,
                 float* __restrict__ z)
{
    unsigned t = blockIdx.x * blockDim.x + threadIdx.x;
    unsigned node = t >> 4;
    unsigned j = (t & 15) << 2;
    if (node >= N_NODES) return;
    const bool active = (j < F);

    float4 acc0 = make_float4(0.f, 0.f, 0.f, 0.f);
    float4 acc1 = make_float4(0.f, 0.f, 0.f, 0.f);
    if (active)
        acc0 = *(const float4*)(h + (size_t)node * F + j);   // self loop

    int i   = rowstart[node];
    int end = i + dege[node];

    for (; i + 4 <= end; i += 4) {
        int p0 = __ldg(&csrc[i + 0]);
        int p1 = __ldg(&csrc[i + 1]);
        int p2 = __ldg(&csrc[i + 2]);
        int p3 = __ldg(&csrc[i + 3]);
        if (active) {
            float4 v0 = __ldg((const float4*)(h + (size_t)p0 * F + j));
            float4 v1 = __ldg((const float4*)(h + (size_t)p1 * F + j));
            float4 v2 = __ldg((const float4*)(h + (size_t)p2 * F + j));
            float4 v3 = __ldg((const float4*)(h + (size_t)p3 * F + j));
            acc0.x += v0.x; acc0.y += v0.y; acc0.z += v0.z; acc0.w += v0.w;
            acc1.x += v1.x; acc1.y += v1.y; acc1.z += v1.z; acc1.w += v1.w;
            acc0.x += v2.x; acc0.y += v2.y; acc0.z += v2.z; acc0.w += v2.w;
            acc1.x += v3.x; acc1.y += v3.y; acc1.z += v3.z; acc1.w += v3.w;
        }
    }
    for (; i < end; i++) {
        int p = __ldg(&csrc[i]);
        if (active) {
            float4 v = __ldg((const float4*)(h + (size_t)p * F + j));
            acc0.x += v.x; acc0.y += v.y; acc0.z += v.z; acc0.w += v.w;
        }
    }

    if (active) {
        float sc = dinv[node];
        float4 b = *(const float4*)(bias + j);
        acc0.x += acc1.x; acc0.y += acc1.y; acc0.z += acc1.z; acc0.w += acc1.w;
        acc0.x = fmaf(acc0.x, sc, b.x);
        acc0.y = fmaf(acc0.y, sc, b.y);
        acc0.z = fmaf(acc0.z, sc, b.z);
        acc0.w = fmaf(acc0.w, sc, b.w);
        if (RELU) {
            acc0.x = fmaxf(acc0.x, 0.f); acc0.y = fmaxf(acc0.y, 0.f);
            acc0.z = fmaxf(acc0.z, 0.f); acc0.w = fmaxf(acc0.w, 0.f);
        }
        *(float4*)(z + (size_t)node * F + j) = acc0;
    }
}

// ---------------- launch ---------------------------------------------------
extern "C" void kernel_launch(void* const* d_in, const int* in_sizes, int n_in,
                              void* d_out, int out_size)
{
    const float* x  = (const float*)d_in[0];
    const int*   ei = (const int*)  d_in[1];
    const float* W1 = (const float*)d_in[2];
    const float* b1 = (const float*)d_in[3];
    const float* W2 = (const float*)d_in[4];
    const float* b2 = (const float*)d_in[5];
    const float* W3 = (const float*)d_in[6];
    const float* b3 = (const float*)d_in[7];
    float* out = (float*)d_out;

    const int* src = ei;              // edge_index[0]
    const int* dst = ei + N_EDGES;    // edge_index[1]

    float *h, *z, *dinv;
    int *dege, *cursor, *rowstart, *csrc, *bsum;
    cudaGetSymbolAddress((void**)&h,        g_h);
    cudaGetSymbolAddress((void**)&z,        g_z);
    cudaGetSymbolAddress((void**)&dinv,     g_dinv);
    cudaGetSymbolAddress((void**)&dege,     g_dege);
    cudaGetSymbolAddress((void**)&cursor,   g_cursor);
    cudaGetSymbolAddress((void**)&rowstart, g_rowstart);
    cudaGetSymbolAddress((void**)&csrc,     g_csrc);
    cudaGetSymbolAddress((void**)&bsum,     g_bsum);

    const int TPB = 256;
    const int edgeBlocks = (N_EDGES + TPB - 1) / TPB;
    const int gemmBlocks = (N_NODES + 127) / 128;
    const int aggBlocks  = ((unsigned)N_NODES * 16 + TPB - 1) / TPB;

    // ---- CSR build + normalization ----
    cudaMemsetAsync(dege, 0, N_NODES * sizeof(int));
    deg_count_k<<<edgeBlocks, TPB>>>(dst, dege);
    scan1_k    <<<SCAN_NB, SCAN_B>>>(dege, rowstart, bsum, dinv, cursor);
    scan2_k    <<<1, 64>>>(bsum);
    scan3_k    <<<SCAN_NB, SCAN_B>>>(rowstart, bsum);
    fill_k     <<<edgeBlocks, TPB>>>(src, dst, rowstart, cursor, csrc);

    // ---- layer 1: x[50000,128] @ W1[128,64] ----
    gemm_scaled_k<<<gemmBlocks, TPB>>>(x, W1, dinv, h, F_IN, F_HID);
    agg_fused_k<F_HID, true><<<aggBlocks, TPB>>>(h, rowstart, dege, csrc, dinv, b1, z);

    // ---- layer 2: z1 @ W2[64,64] ----
    gemm_scaled_k<<<gemmBlocks, TPB>>>(z, W2, dinv, h, F_HID, F_HID);
    agg_fused_k<F_HID, true><<<aggBlocks, TPB>>>(h, rowstart, dege, csrc, dinv, b2, z);

    // ---- layer 3: z2 @ W3[64,40] -> d_out ----
    gemm_scaled_k<<<gemmBlocks, TPB>>>(z, W3, dinv, h, F_HID, F_OUT);
    agg_fused_k<F_OUT, false><<<aggBlocks, TPB>>>(h, rowstart, dege, csrc, dinv, b3, out);
}